// round 6
// baseline (speedup 1.0000x reference)
#include <cuda_runtime.h>
#include <cuda_bf16.h>
#include <cstdint>

#define N_NODES 100000
#define N_EDGES 1600000
#define HDIM 128
#define EDIM 32
#define KDIM 288                 // 128(x) + 128(Sx) + 32(Se) = 9 * 32
#define NCHUNK 9
#define N_TILES ((N_NODES + 127) / 128)   // 782
#define NB 98

// ---------------- device scratch (allocation-free rule) ----------------
__device__ int   g_deg[N_NODES];
__device__ int   g_off[N_NODES];
__device__ int   g_bsum[NB];
__device__ int2  g_rec[N_EDGES];
__device__ __nv_bfloat16 g_Wt_hi[HDIM * KDIM];  // [j][k] = Wcat[k][j] hi
__device__ __nv_bfloat16 g_Wt_lo[HDIM * KDIM];  // residual lo

// ---------------- helpers ----------------
__device__ __forceinline__ uint32_t smem_u32(const void* p) {
    uint32_t a;
    asm("{ .reg .u64 t; cvta.to.shared.u64 t, %1; cvt.u32.u64 %0, t; }"
        : "=r"(a) : "l"(p));
    return a;
}
__device__ __forceinline__ uint32_t pk2(float a, float b) {
    __nv_bfloat162 t = __floats2bfloat162_rn(a, b);
    return *reinterpret_cast<uint32_t*>(&t);
}
__device__ __forceinline__ void ldsm_x4(uint32_t* r, uint32_t addr) {
    asm volatile("ldmatrix.sync.aligned.m8n8.x4.shared.b16 {%0,%1,%2,%3}, [%4];"
                 : "=r"(r[0]), "=r"(r[1]), "=r"(r[2]), "=r"(r[3]) : "r"(addr));
}
__device__ __forceinline__ void ldsm_x2(uint32_t* r, uint32_t addr) {
    asm volatile("ldmatrix.sync.aligned.m8n8.x2.shared.b16 {%0,%1}, [%2];"
                 : "=r"(r[0]), "=r"(r[1]) : "r"(addr));
}
__device__ __forceinline__ void mma16816(float* d, const uint32_t* a,
                                         const uint32_t* b) {
    asm volatile(
        "mma.sync.aligned.m16n8k16.row.col.f32.bf16.bf16.f32 "
        "{%0,%1,%2,%3}, {%4,%5,%6,%7}, {%8,%9}, {%0,%1,%2,%3};"
        : "+f"(d[0]), "+f"(d[1]), "+f"(d[2]), "+f"(d[3])
        : "r"(a[0]), "r"(a[1]), "r"(a[2]), "r"(a[3]), "r"(b[0]), "r"(b[1]));
}

// fused-kernel smem layout (bytes)
// A tile: full K=288 per row, pitch 592B (148 words == 20 mod 32 -> ldsm
// conflict-free), 128 rows. hi + lo copies.
#define APITCH 592
#define AHI 0
#define ALO 75776
#define BHI 151552            // B chunk buffer: 128 rows x 80B pitch
#define BLO 161792
#define BSO 172032
#define BMO 172544
#define SDEG 173056
#define SMEM_TOTAL 173568

// ===========================================================================
// 0) prep: zero degree histogram + transpose/split weights (fused)
// ===========================================================================
__global__ void prep_kernel(const float* __restrict__ Wself,
                            const float* __restrict__ Wmsg) {
    int i = blockIdx.x * blockDim.x + threadIdx.x;
    if (i < N_NODES) g_deg[i] = 0;
    if (i < HDIM * KDIM) {
        int j = i / KDIM, k = i % KDIM;
        float v = (k < HDIM) ? Wself[k * HDIM + j] : Wmsg[(k - HDIM) * HDIM + j];
        __nv_bfloat16 h = __float2bfloat16(v);
        g_Wt_hi[i] = h;
        g_Wt_lo[i] = __float2bfloat16(v - __bfloat162float(h));
    }
}

// ===========================================================================
// 1) degree histogram
// ===========================================================================
__global__ void hist_kernel(const int* __restrict__ ei) {
    int e = blockIdx.x * blockDim.x + threadIdx.x;
    if (e < N_EDGES) atomicAdd(&g_deg[__ldg(&ei[N_EDGES + e])], 1);
}

// ===========================================================================
// 2) scan (block-local excl in g_off, block sums scanned in g_bsum)
// ===========================================================================
__device__ __forceinline__ int warp_incl_scan(int v, int lane) {
#pragma unroll
    for (int d = 1; d < 32; d <<= 1) {
        int t = __shfl_up_sync(0xffffffffu, v, d);
        if (lane >= d) v += t;
    }
    return v;
}
__global__ void scan1_kernel() {
    __shared__ int wsum[32];
    int i = blockIdx.x * 1024 + threadIdx.x;
    int lane = threadIdx.x & 31, w = threadIdx.x >> 5;
    int v = (i < N_NODES) ? g_deg[i] : 0;
    int inc = warp_incl_scan(v, lane);
    if (lane == 31) wsum[w] = inc;
    __syncthreads();
    if (w == 0) {
        int s = wsum[lane];
        int si = warp_incl_scan(s, lane);
        wsum[lane] = si - s;
    }
    __syncthreads();
    int excl = inc - v + wsum[w];
    if (i < N_NODES) g_off[i] = excl;              // block-local exclusive
    if (threadIdx.x == 1023) g_bsum[blockIdx.x] = excl + v;
}
__global__ void scan2_kernel() {
    __shared__ int wsum[4];
    int i = threadIdx.x;
    int lane = i & 31, w = i >> 5;
    int v = (i < NB) ? g_bsum[i] : 0;
    int inc = warp_incl_scan(v, lane);
    if (lane == 31) wsum[w] = inc;
    __syncthreads();
    if (i == 0) {
        int c = 0;
#pragma unroll
        for (int k = 0; k < 4; k++) { int t = wsum[k]; wsum[k] = c; c += t; }
    }
    __syncthreads();
    if (i < NB) g_bsum[i] = inc - v + wsum[w];     // exclusive block bases
}

// ===========================================================================
// 3) reorder: ticket = block-local atomic + scanned block base
//    afterwards g_off[n] = block_local_excl(n) + deg(n)
// ===========================================================================
__global__ void reorder_kernel(const int* __restrict__ ei) {
    int e = blockIdx.x * blockDim.x + threadIdx.x;
    if (e >= N_EDGES) return;
    int src = __ldg(&ei[e]);
    int dst = __ldg(&ei[N_EDGES + e]);
    int pos = atomicAdd(&g_off[dst], 1) + __ldg(&g_bsum[dst >> 10]);
    g_rec[pos] = make_int2(src, e);
}

// ===========================================================================
// 4) fused gather + mma.sync bf16 2-split GEMM + bias + relu
// ===========================================================================
__global__ void __launch_bounds__(256)
fused_gemm(const float* __restrict__ x,
           const float* __restrict__ ea,
           const float* __restrict__ bself,
           const float* __restrict__ bmsg,
           float* __restrict__ out) {
    extern __shared__ __align__(16) unsigned char sm[];
    const uint32_t sbase = smem_u32(sm);

    const int tid = threadIdx.x;
    const int lane = tid & 31;
    const int wid = tid >> 5;
    const int warp_m = wid & 3;
    const int warp_n = wid >> 2;
    const int n0 = blockIdx.x * 128;

    float* bs = reinterpret_cast<float*>(sm + BSO);
    float* bm = reinterpret_cast<float*>(sm + BMO);
    float* sdeg = reinterpret_cast<float*>(sm + SDEG);
    if (tid < HDIM) { bs[tid] = bself[tid]; bm[tid] = bmsg[tid]; }

    // ---------- phase 1a: stage x chunk (k 0..127) into A hi/lo ----------
    {
        const int row = tid >> 1;
        const int half = tid & 1;
        const int gn = n0 + row;
        const bool valid = (gn < N_NODES);
#pragma unroll
        for (int j = 0; j < 16; j++) {
            int k = half * 64 + j * 4;
            float4 f = valid
                ? __ldg(reinterpret_cast<const float4*>(x + (size_t)gn * HDIM + k))
                : make_float4(0.f, 0.f, 0.f, 0.f);
            __nv_bfloat16 h0 = __float2bfloat16(f.x), h1 = __float2bfloat16(f.y);
            __nv_bfloat16 h2 = __float2bfloat16(f.z), h3 = __float2bfloat16(f.w);
            uint2 hv, lv;
            hv.x = pk2(__bfloat162float(h0), __bfloat162float(h1));
            hv.y = pk2(__bfloat162float(h2), __bfloat162float(h3));
            lv.x = pk2(f.x - __bfloat162float(h0), f.y - __bfloat162float(h1));
            lv.y = pk2(f.z - __bfloat162float(h2), f.w - __bfloat162float(h3));
            uint32_t o = row * APITCH + k * 2;
            *reinterpret_cast<uint2*>(sm + AHI + o) = hv;
            *reinterpret_cast<uint2*>(sm + ALO + o) = lv;
        }
    }

    // ---------- phase 1b: gather Sx/Se per node (warp per node) ----------
    for (int r = wid; r < 128; r += 8) {
        const int gn = n0 + r;
        float4 ax = make_float4(0.f, 0.f, 0.f, 0.f);
        float4 ae = make_float4(0.f, 0.f, 0.f, 0.f);
        int beg = 0, end = 0;
        if (gn < N_NODES) {
            beg = (gn == 0) ? 0
                : __ldg(&g_off[gn - 1]) + __ldg(&g_bsum[(gn - 1) >> 10]);
            end = __ldg(&g_off[gn]) + __ldg(&g_bsum[gn >> 10]);
        }
        int i = beg;
        // 4-deep pipeline: enough MLP with only 8 warps/SM
        for (; i + 3 < end; i += 4) {
            int2 r0 = __ldg(&g_rec[i]);
            int2 r1 = __ldg(&g_rec[i + 1]);
            int2 r2 = __ldg(&g_rec[i + 2]);
            int2 r3 = __ldg(&g_rec[i + 3]);
            float4 v0 = __ldg(&reinterpret_cast<const float4*>(x + (size_t)r0.x * HDIM)[lane]);
            float4 v1 = __ldg(&reinterpret_cast<const float4*>(x + (size_t)r1.x * HDIM)[lane]);
            float4 v2 = __ldg(&reinterpret_cast<const float4*>(x + (size_t)r2.x * HDIM)[lane]);
            float4 v3 = __ldg(&reinterpret_cast<const float4*>(x + (size_t)r3.x * HDIM)[lane]);
            ax.x += (v0.x + v1.x) + (v2.x + v3.x);
            ax.y += (v0.y + v1.y) + (v2.y + v3.y);
            ax.z += (v0.z + v1.z) + (v2.z + v3.z);
            ax.w += (v0.w + v1.w) + (v2.w + v3.w);
            if (lane < 8) {
                float4 w0 = __ldg(&reinterpret_cast<const float4*>(ea + (size_t)r0.y * EDIM)[lane]);
                float4 w1 = __ldg(&reinterpret_cast<const float4*>(ea + (size_t)r1.y * EDIM)[lane]);
                float4 w2 = __ldg(&reinterpret_cast<const float4*>(ea + (size_t)r2.y * EDIM)[lane]);
                float4 w3 = __ldg(&reinterpret_cast<const float4*>(ea + (size_t)r3.y * EDIM)[lane]);
                ae.x += (w0.x + w1.x) + (w2.x + w3.x);
                ae.y += (w0.y + w1.y) + (w2.y + w3.y);
                ae.z += (w0.z + w1.z) + (w2.z + w3.z);
                ae.w += (w0.w + w1.w) + (w2.w + w3.w);
            }
        }
        for (; i < end; i++) {
            int2 r0 = __ldg(&g_rec[i]);
            float4 v0 = __ldg(&reinterpret_cast<const float4*>(x + (size_t)r0.x * HDIM)[lane]);
            ax.x += v0.x; ax.y += v0.y; ax.z += v0.z; ax.w += v0.w;
            if (lane < 8) {
                float4 w0 = __ldg(&reinterpret_cast<const float4*>(ea + (size_t)r0.y * EDIM)[lane]);
                ae.x += w0.x; ae.y += w0.y; ae.z += w0.z; ae.w += w0.w;
            }
        }
        // Sx -> k in [128,256): lane covers k = 128 + lane*4 .. +3
        {
            __nv_bfloat16 h0 = __float2bfloat16(ax.x), h1 = __float2bfloat16(ax.y);
            __nv_bfloat16 h2 = __float2bfloat16(ax.z), h3 = __float2bfloat16(ax.w);
            uint2 hv, lv;
            hv.x = pk2(__bfloat162float(h0), __bfloat162float(h1));
            hv.y = pk2(__bfloat162float(h2), __bfloat162float(h3));
            lv.x = pk2(ax.x - __bfloat162float(h0), ax.y - __bfloat162float(h1));
            lv.y = pk2(ax.z - __bfloat162float(h2), ax.w - __bfloat162float(h3));
            uint32_t o = r * APITCH + (128 + lane * 4) * 2;
            *reinterpret_cast<uint2*>(sm + AHI + o) = hv;
            *reinterpret_cast<uint2*>(sm + ALO + o) = lv;
        }
        // Se -> k in [256,288): lanes 0..7
        if (lane < 8) {
            __nv_bfloat16 h0 = __float2bfloat16(ae.x), h1 = __float2bfloat16(ae.y);
            __nv_bfloat16 h2 = __float2bfloat16(ae.z), h3 = __float2bfloat16(ae.w);
            uint2 hv, lv;
            hv.x = pk2(__bfloat162float(h0), __bfloat162float(h1));
            hv.y = pk2(__bfloat162float(h2), __bfloat162float(h3));
            lv.x = pk2(ae.x - __bfloat162float(h0), ae.y - __bfloat162float(h1));
            lv.y = pk2(ae.z - __bfloat162float(h2), ae.w - __bfloat162float(h3));
            uint32_t o = r * APITCH + (256 + lane * 4) * 2;
            *reinterpret_cast<uint2*>(sm + AHI + o) = hv;
            *reinterpret_cast<uint2*>(sm + ALO + o) = lv;
        }
        if (lane == 0) sdeg[r] = (float)(end - beg);
    }

    // ---------- phase 2: MMA over 9 chunks, B reg-prefetch pipeline ------
    uint4 bhv[2], blv[2];
    auto stageB = [&](int c) {
#pragma unroll
        for (int t = 0; t < 2; t++) {
            int q = tid + t * 256;
            int j = q >> 2, sub = q & 3;
            size_t o = (size_t)j * KDIM + c * 32 + sub * 8;
            bhv[t] = *reinterpret_cast<const uint4*>(g_Wt_hi + o);
            blv[t] = *reinterpret_cast<const uint4*>(g_Wt_lo + o);
        }
    };
    auto commitB = [&]() {
#pragma unroll
        for (int t = 0; t < 2; t++) {
            int q = tid + t * 256;
            int j = q >> 2, sub = q & 3;
            *reinterpret_cast<uint4*>(sm + BHI + j * 80 + sub * 16) = bhv[t];
            *reinterpret_cast<uint4*>(sm + BLO + j * 80 + sub * 16) = blv[t];
        }
    };

    float acc[2][8][4];
#pragma unroll
    for (int a = 0; a < 2; a++)
#pragma unroll
        for (int b = 0; b < 8; b++)
#pragma unroll
            for (int c = 0; c < 4; c++) acc[a][b][c] = 0.f;

    const uint32_t a_row_off =
        (warp_m * 32 + (lane & 15)) * APITCH + (lane >> 4) * 16;
    const uint32_t b_row_off =
        (warp_n * 64 + (lane & 7)) * 80 + ((lane >> 3) & 1) * 16;

    stageB(0);
    __syncthreads();           // A tile + biases + sdeg visible
    commitB();
    __syncthreads();

    for (int c = 0; c < NCHUNK; c++) {
        if (c + 1 < NCHUNK) stageB(c + 1);

#pragma unroll
        for (int ks = 0; ks < 2; ks++) {
            uint32_t ah[2][4], al[2][4];
#pragma unroll
            for (int mf = 0; mf < 2; mf++) {
                uint32_t ao = a_row_off + mf * 16 * APITCH + c * 64 + ks * 32;
                ldsm_x4(ah[mf], sbase + AHI + ao);
                ldsm_x4(al[mf], sbase + ALO + ao);
            }
#pragma unroll
            for (int nf = 0; nf < 8; nf++) {
                uint32_t bo = b_row_off + nf * 8 * 80 + ks * 32;
                uint32_t bh[2], bl[2];
                ldsm_x2(bh, sbase + BHI + bo);
                ldsm_x2(bl, sbase + BLO + bo);
#pragma unroll
                for (int mf = 0; mf < 2; mf++) {
                    mma16816(acc[mf][nf], ah[mf], bh);
                    mma16816(acc[mf][nf], ah[mf], bl);
                    mma16816(acc[mf][nf], al[mf], bh);
                }
            }
        }
        __syncthreads();
        if (c + 1 < NCHUNK) {
            commitB();
            __syncthreads();
        }
    }

    // ---------- epilogue ----------
    const int gid = lane >> 2, tig = lane & 3;
#pragma unroll
    for (int mf = 0; mf < 2; mf++) {
#pragma unroll
        for (int rr = 0; rr < 2; rr++) {
            int row = warp_m * 32 + mf * 16 + rr * 8 + gid;
            int gn = n0 + row;
            if (gn >= N_NODES) continue;
            float degf = sdeg[row];
#pragma unroll
            for (int nf = 0; nf < 8; nf++) {
                int j = warp_n * 64 + nf * 8 + tig * 2;
                float2 o;
                o.x = fmaxf(acc[mf][nf][rr * 2 + 0] + bs[j]     + degf * bm[j],     0.f);
                o.y = fmaxf(acc[mf][nf][rr * 2 + 1] + bs[j + 1] + degf * bm[j + 1], 0.f);
                *reinterpret_cast<float2*>(out + (size_t)gn * HDIM + j) = o;
            }
        }
    }
}

// ---------------------------------------------------------------------------
extern "C" void kernel_launch(void* const* d_in, const int* in_sizes, int n_in,
                              void* d_out, int out_size) {
    const float* x     = (const float*)d_in[0];
    const int*   ei    = (const int*)  d_in[1];
    const float* ea    = (const float*)d_in[2];
    const float* Wself = (const float*)d_in[3];
    const float* bself = (const float*)d_in[4];
    const float* Wmsg  = (const float*)d_in[5];
    const float* bmsg  = (const float*)d_in[6];
    float* out = (float*)d_out;

    cudaFuncSetAttribute(fused_gemm,
                         cudaFuncAttributeMaxDynamicSharedMemorySize, SMEM_TOTAL);

    prep_kernel<<<(N_NODES + 255) / 256, 256>>>(Wself, Wmsg);       // 0
    hist_kernel<<<(N_EDGES + 511) / 512, 512>>>(ei);                // 1
    scan1_kernel<<<NB, 1024>>>();                                   // 2
    scan2_kernel<<<1, 128>>>();                                     // 3
    reorder_kernel<<<(N_EDGES + 511) / 512, 512>>>(ei);             // 4
    fused_gemm<<<N_TILES, 256, SMEM_TOTAL>>>(x, ea, bself, bmsg, out); // 5 (ncu -s 5)
}

// round 7
// speedup vs baseline: 2.2801x; 2.2801x over previous
#include <cuda_runtime.h>
#include <cuda_bf16.h>
#include <cstdint>

#define N_NODES 100000
#define N_EDGES 1600000
#define HDIM 128
#define EDIM 32
#define KDIM 288                 // 128 + 128 + 32 = 9 * 32
#define NCHUNK 9
#define N_TILES ((N_NODES + 127) / 128)   // 782
#define NB 98

// ---------------- device scratch (allocation-free rule) ----------------
__device__ float g_Sx[N_NODES * HDIM];
__device__ float g_Se[N_NODES * EDIM];
__device__ int   g_deg[N_NODES];
__device__ int   g_off[N_NODES];
__device__ int   g_bsum[NB];
__device__ int2  g_rec[N_EDGES];
__device__ __nv_bfloat16 g_Wt_hi[HDIM * KDIM];  // [j][k] = Wcat[k][j] hi
__device__ __nv_bfloat16 g_Wt_lo[HDIM * KDIM];  // residual lo

// ---------------- helpers ----------------
__device__ __forceinline__ uint32_t smem_u32(const void* p) {
    uint32_t a;
    asm("{ .reg .u64 t; cvta.to.shared.u64 t, %1; cvt.u32.u64 %0, t; }"
        : "=r"(a) : "l"(p));
    return a;
}
__device__ __forceinline__ uint32_t pk2(float a, float b) {
    __nv_bfloat162 t = __floats2bfloat162_rn(a, b);
    return *reinterpret_cast<uint32_t*>(&t);
}
__device__ __forceinline__ void ldsm_x4(uint32_t* r, uint32_t addr) {
    asm volatile("ldmatrix.sync.aligned.m8n8.x4.shared.b16 {%0,%1,%2,%3}, [%4];"
                 : "=r"(r[0]), "=r"(r[1]), "=r"(r[2]), "=r"(r[3]) : "r"(addr));
}
__device__ __forceinline__ void ldsm_x2(uint32_t* r, uint32_t addr) {
    asm volatile("ldmatrix.sync.aligned.m8n8.x2.shared.b16 {%0,%1}, [%2];"
                 : "=r"(r[0]), "=r"(r[1]) : "r"(addr));
}
__device__ __forceinline__ void mma16816(float* d, const uint32_t* a,
                                         const uint32_t* b) {
    asm volatile(
        "mma.sync.aligned.m16n8k16.row.col.f32.bf16.bf16.f32 "
        "{%0,%1,%2,%3}, {%4,%5,%6,%7}, {%8,%9}, {%0,%1,%2,%3};"
        : "+f"(d[0]), "+f"(d[1]), "+f"(d[2]), "+f"(d[3])
        : "r"(a[0]), "r"(a[1]), "r"(a[2]), "r"(a[3]), "r"(b[0]), "r"(b[1]));
}

// GEMM smem layout (bytes). Rows padded 32->40 bf16 (80B).
#define AHI 0
#define ALO 10240
#define BHI 20480
#define BLO 30720
#define BSO 40960
#define BMO 41472
#define SMEM_TOTAL 41984

// ===========================================================================
// 0) prep: zero degree histogram + transpose/split weights (fused)
// ===========================================================================
__global__ void prep_kernel(const float* __restrict__ Wself,
                            const float* __restrict__ Wmsg) {
    int i = blockIdx.x * blockDim.x + threadIdx.x;
    if (i < N_NODES) g_deg[i] = 0;
    if (i < HDIM * KDIM) {
        int j = i / KDIM, k = i % KDIM;
        float v = (k < HDIM) ? Wself[k * HDIM + j] : Wmsg[(k - HDIM) * HDIM + j];
        __nv_bfloat16 h = __float2bfloat16(v);
        g_Wt_hi[i] = h;
        g_Wt_lo[i] = __float2bfloat16(v - __bfloat162float(h));
    }
}

// ===========================================================================
// 1) degree histogram
// ===========================================================================
__global__ void hist_kernel(const int* __restrict__ ei) {
    int e = blockIdx.x * blockDim.x + threadIdx.x;
    if (e < N_EDGES) atomicAdd(&g_deg[__ldg(&ei[N_EDGES + e])], 1);
}

// ===========================================================================
// 2) scan: block-local exclusive in g_off, scanned block bases in g_bsum
// ===========================================================================
__device__ __forceinline__ int warp_incl_scan(int v, int lane) {
#pragma unroll
    for (int d = 1; d < 32; d <<= 1) {
        int t = __shfl_up_sync(0xffffffffu, v, d);
        if (lane >= d) v += t;
    }
    return v;
}
__global__ void scan1_kernel() {
    __shared__ int wsum[32];
    int i = blockIdx.x * 1024 + threadIdx.x;
    int lane = threadIdx.x & 31, w = threadIdx.x >> 5;
    int v = (i < N_NODES) ? g_deg[i] : 0;
    int inc = warp_incl_scan(v, lane);
    if (lane == 31) wsum[w] = inc;
    __syncthreads();
    if (w == 0) {
        int s = wsum[lane];
        int si = warp_incl_scan(s, lane);
        wsum[lane] = si - s;
    }
    __syncthreads();
    int excl = inc - v + wsum[w];
    if (i < N_NODES) g_off[i] = excl;              // block-local exclusive
    if (threadIdx.x == 1023) g_bsum[blockIdx.x] = excl + v;
}
__global__ void scan2_kernel() {
    __shared__ int wsum[4];
    int i = threadIdx.x;
    int lane = i & 31, w = i >> 5;
    int v = (i < NB) ? g_bsum[i] : 0;
    int inc = warp_incl_scan(v, lane);
    if (lane == 31) wsum[w] = inc;
    __syncthreads();
    if (i == 0) {
        int c = 0;
#pragma unroll
        for (int k = 0; k < 4; k++) { int t = wsum[k]; wsum[k] = c; c += t; }
    }
    __syncthreads();
    if (i < NB) g_bsum[i] = inc - v + wsum[w];     // exclusive block bases
}

// ===========================================================================
// 3) reorder: ticket = block-local atomic + scanned block base.
//    After this, g_off[n] = block_local_exclusive(n) + deg(n).
//    Global end(n)  = g_off[n]   + g_bsum[n >> 10]
//    Global beg(n)  = (n == 0) ? 0 : g_off[n-1] + g_bsum[(n-1) >> 10]
// ===========================================================================
__global__ void reorder_kernel(const int* __restrict__ ei) {
    int e = blockIdx.x * blockDim.x + threadIdx.x;
    if (e >= N_EDGES) return;
    int src = __ldg(&ei[e]);
    int dst = __ldg(&ei[N_EDGES + e]);
    int pos = atomicAdd(&g_off[dst], 1) + __ldg(&g_bsum[dst >> 10]);
    g_rec[pos] = make_int2(src, e);
}

// ===========================================================================
// 4) gather-accumulate: one warp per dst node, register accumulation,
//    4-deep edge pipeline, single coalesced store. NO atomics.
// ===========================================================================
__global__ void __launch_bounds__(256)
gather_kernel(const float* __restrict__ x, const float* __restrict__ ea) {
    int gw   = (blockIdx.x * blockDim.x + threadIdx.x) >> 5;
    int lane = threadIdx.x & 31;
    int nw   = (gridDim.x * blockDim.x) >> 5;
    for (int n = gw; n < N_NODES; n += nw) {
        int beg = (n == 0) ? 0
                : __ldg(&g_off[n - 1]) + __ldg(&g_bsum[(n - 1) >> 10]);
        int end = __ldg(&g_off[n]) + __ldg(&g_bsum[n >> 10]);
        float4 ax = make_float4(0.f, 0.f, 0.f, 0.f);
        float4 ae = make_float4(0.f, 0.f, 0.f, 0.f);
        int i = beg;
        for (; i + 3 < end; i += 4) {
            int2 r0 = __ldg(&g_rec[i]);
            int2 r1 = __ldg(&g_rec[i + 1]);
            int2 r2 = __ldg(&g_rec[i + 2]);
            int2 r3 = __ldg(&g_rec[i + 3]);
            float4 v0 = __ldg(&reinterpret_cast<const float4*>(x + (size_t)r0.x * HDIM)[lane]);
            float4 v1 = __ldg(&reinterpret_cast<const float4*>(x + (size_t)r1.x * HDIM)[lane]);
            float4 v2 = __ldg(&reinterpret_cast<const float4*>(x + (size_t)r2.x * HDIM)[lane]);
            float4 v3 = __ldg(&reinterpret_cast<const float4*>(x + (size_t)r3.x * HDIM)[lane]);
            ax.x += (v0.x + v1.x) + (v2.x + v3.x);
            ax.y += (v0.y + v1.y) + (v2.y + v3.y);
            ax.z += (v0.z + v1.z) + (v2.z + v3.z);
            ax.w += (v0.w + v1.w) + (v2.w + v3.w);
            if (lane < 8) {
                float4 w0 = __ldg(&reinterpret_cast<const float4*>(ea + (size_t)r0.y * EDIM)[lane]);
                float4 w1 = __ldg(&reinterpret_cast<const float4*>(ea + (size_t)r1.y * EDIM)[lane]);
                float4 w2 = __ldg(&reinterpret_cast<const float4*>(ea + (size_t)r2.y * EDIM)[lane]);
                float4 w3 = __ldg(&reinterpret_cast<const float4*>(ea + (size_t)r3.y * EDIM)[lane]);
                ae.x += (w0.x + w1.x) + (w2.x + w3.x);
                ae.y += (w0.y + w1.y) + (w2.y + w3.y);
                ae.z += (w0.z + w1.z) + (w2.z + w3.z);
                ae.w += (w0.w + w1.w) + (w2.w + w3.w);
            }
        }
        for (; i < end; i++) {
            int2 r0 = __ldg(&g_rec[i]);
            float4 v0 = __ldg(&reinterpret_cast<const float4*>(x + (size_t)r0.x * HDIM)[lane]);
            ax.x += v0.x; ax.y += v0.y; ax.z += v0.z; ax.w += v0.w;
            if (lane < 8) {
                float4 w0 = __ldg(&reinterpret_cast<const float4*>(ea + (size_t)r0.y * EDIM)[lane]);
                ae.x += w0.x; ae.y += w0.y; ae.z += w0.z; ae.w += w0.w;
            }
        }
        reinterpret_cast<float4*>(g_Sx + (size_t)n * HDIM)[lane] = ax;
        if (lane < 8)
            reinterpret_cast<float4*>(g_Se + (size_t)n * EDIM)[lane] = ae;
    }
}

// ===========================================================================
// 5) mma.sync bf16 2-split GEMM (R5-proven): 128x128 tile, 42KB smem
// ===========================================================================
__global__ void __launch_bounds__(256)
node_gemm_mma(const float* __restrict__ x,
              const float* __restrict__ bself,
              const float* __restrict__ bmsg,
              float* __restrict__ out) {
    __shared__ __align__(16) unsigned char sm[SMEM_TOTAL];
    const uint32_t sbase = smem_u32(sm);

    const int tid = threadIdx.x;
    const int lane = tid & 31;
    const int wid = tid >> 5;
    const int warp_m = wid & 3;
    const int warp_n = wid >> 2;

    float* bs = reinterpret_cast<float*>(sm + BSO);
    float* bm = reinterpret_cast<float*>(sm + BMO);
    if (tid < HDIM) { bs[tid] = bself[tid]; bm[tid] = bmsg[tid]; }

    const int n0 = blockIdx.x * 128;

    const int kp = tid & 15;
    const int arow0 = tid >> 4;
    float2 av[8];
    uint4 bhv[2], blv[2];

    float acc[2][8][4];
#pragma unroll
    for (int a = 0; a < 2; a++)
#pragma unroll
        for (int b = 0; b < 8; b++)
#pragma unroll
            for (int c = 0; c < 4; c++) acc[a][b][c] = 0.f;

    auto stage = [&](int c) {
        const int kb = c * 32;
        const float* asrc;
        int astr;
        if (kb < 128)      { asrc = x    + kb;       astr = HDIM; }
        else if (kb < 256) { asrc = g_Sx + kb - 128; astr = HDIM; }
        else               { asrc = g_Se;            astr = EDIM; }
#pragma unroll
        for (int t = 0; t < 8; t++) {
            int gn = n0 + arow0 + t * 16;
            av[t] = (gn < N_NODES)
                ? *reinterpret_cast<const float2*>(asrc + (size_t)gn * astr + kp * 2)
                : make_float2(0.f, 0.f);
        }
#pragma unroll
        for (int t = 0; t < 2; t++) {
            int q = tid + t * 256;
            int j = q >> 2, sub = q & 3;
            size_t o = (size_t)j * KDIM + kb + sub * 8;
            bhv[t] = *reinterpret_cast<const uint4*>(g_Wt_hi + o);
            blv[t] = *reinterpret_cast<const uint4*>(g_Wt_lo + o);
        }
    };
    auto commit = [&]() {
#pragma unroll
        for (int t = 0; t < 8; t++) {
            int row = arow0 + t * 16;
            float vx = av[t].x, vy = av[t].y;
            __nv_bfloat16 hx = __float2bfloat16(vx);
            __nv_bfloat16 hy = __float2bfloat16(vy);
            float lx = vx - __bfloat162float(hx);
            float ly = vy - __bfloat162float(hy);
            __nv_bfloat162 hp; hp.x = hx; hp.y = hy;
            *reinterpret_cast<uint32_t*>(sm + AHI + row * 80 + kp * 4) =
                *reinterpret_cast<uint32_t*>(&hp);
            *reinterpret_cast<uint32_t*>(sm + ALO + row * 80 + kp * 4) =
                pk2(lx, ly);
        }
#pragma unroll
        for (int t = 0; t < 2; t++) {
            int q = tid + t * 256;
            int j = q >> 2, sub = q & 3;
            *reinterpret_cast<uint4*>(sm + BHI + j * 80 + sub * 16) = bhv[t];
            *reinterpret_cast<uint4*>(sm + BLO + j * 80 + sub * 16) = blv[t];
        }
    };

    const uint32_t a_row_off = (warp_m * 32 + (lane & 15)) * 80 + (lane >> 4) * 16;
    const uint32_t b_row_off = (warp_n * 64 + (lane & 7)) * 80 + ((lane >> 3) & 1) * 16;

    stage(0);
    __syncthreads();
    commit();
    __syncthreads();

    for (int c = 0; c < NCHUNK; c++) {
        if (c + 1 < NCHUNK) stage(c + 1);

#pragma unroll
        for (int ks = 0; ks < 2; ks++) {
            uint32_t ah[2][4], al[2][4];
#pragma unroll
            for (int mf = 0; mf < 2; mf++) {
                uint32_t ao = a_row_off + mf * 16 * 80 + ks * 32;
                ldsm_x4(ah[mf], sbase + AHI + ao);
                ldsm_x4(al[mf], sbase + ALO + ao);
            }
#pragma unroll
            for (int nf = 0; nf < 8; nf++) {
                uint32_t bo = b_row_off + nf * 8 * 80 + ks * 32;
                uint32_t bh[2], bl[2];
                ldsm_x2(bh, sbase + BHI + bo);
                ldsm_x2(bl, sbase + BLO + bo);
#pragma unroll
                for (int mf = 0; mf < 2; mf++) {
                    mma16816(acc[mf][nf], ah[mf], bh);
                    mma16816(acc[mf][nf], ah[mf], bl);
                    mma16816(acc[mf][nf], al[mf], bh);
                }
            }
        }
        __syncthreads();
        if (c + 1 < NCHUNK) {
            commit();
            __syncthreads();
        }
    }

    const int gid = lane >> 2, tig = lane & 3;
#pragma unroll
    for (int mf = 0; mf < 2; mf++) {
#pragma unroll
        for (int rr = 0; rr < 2; rr++) {
            int row = warp_m * 32 + mf * 16 + rr * 8 + gid;
            int gn = n0 + row;
            if (gn >= N_NODES) continue;
            float degf = (float)g_deg[gn];
#pragma unroll
            for (int nf = 0; nf < 8; nf++) {
                int j = warp_n * 64 + nf * 8 + tig * 2;
                float2 o;
                o.x = fmaxf(acc[mf][nf][rr * 2 + 0] + bs[j]     + degf * bm[j],     0.f);
                o.y = fmaxf(acc[mf][nf][rr * 2 + 1] + bs[j + 1] + degf * bm[j + 1], 0.f);
                *reinterpret_cast<float2*>(out + (size_t)gn * HDIM + j) = o;
            }
        }
    }
}

// ---------------------------------------------------------------------------
extern "C" void kernel_launch(void* const* d_in, const int* in_sizes, int n_in,
                              void* d_out, int out_size) {
    const float* x     = (const float*)d_in[0];
    const int*   ei    = (const int*)  d_in[1];
    const float* ea    = (const float*)d_in[2];
    const float* Wself = (const float*)d_in[3];
    const float* bself = (const float*)d_in[4];
    const float* Wmsg  = (const float*)d_in[5];
    const float* bmsg  = (const float*)d_in[6];
    float* out = (float*)d_out;

    prep_kernel<<<(N_NODES + 255) / 256, 256>>>(Wself, Wmsg);       // 0
    hist_kernel<<<(N_EDGES + 511) / 512, 512>>>(ei);                // 1
    scan1_kernel<<<NB, 1024>>>();                                   // 2
    scan2_kernel<<<1, 128>>>();                                     // 3
    reorder_kernel<<<(N_EDGES + 511) / 512, 512>>>(ei);             // 4
    gather_kernel<<<148 * 12, 256>>>(x, ea);                        // 5 (ncu -s 5)
    node_gemm_mma<<<N_TILES, 256>>>(x, bself, bmsg, out);           // 6
}

// round 8
// speedup vs baseline: 2.5903x; 1.1360x over previous
#include <cuda_runtime.h>
#include <cuda_bf16.h>
#include <cuda_fp16.h>
#include <cstdint>

#define N_NODES 100000
#define N_EDGES 1600000
#define HDIM 128
#define EDIM 32
#define KDIM 288                 // 128 + 128 + 32 = 9 * 32
#define NCHUNK 9
#define N_TILES ((N_NODES + 127) / 128)   // 782
#define NB 98

// ---------------- device scratch (allocation-free rule) ----------------
__device__ float  g_Sx[N_NODES * HDIM];
__device__ float  g_Se[N_NODES * EDIM];
__device__ __half g_xh[N_NODES * HDIM];   // fp16 copy of x for the gather
__device__ int    g_deg[N_NODES];
__device__ int    g_off[N_NODES];
__device__ int    g_bsum[NB];
__device__ int2   g_rec[N_EDGES];
__device__ __nv_bfloat16 g_Wt_hi[HDIM * KDIM];  // [j][k] = Wcat[k][j] hi
__device__ __nv_bfloat16 g_Wt_lo[HDIM * KDIM];  // residual lo

// ---------------- helpers ----------------
__device__ __forceinline__ uint32_t smem_u32(const void* p) {
    uint32_t a;
    asm("{ .reg .u64 t; cvta.to.shared.u64 t, %1; cvt.u32.u64 %0, t; }"
        : "=r"(a) : "l"(p));
    return a;
}
__device__ __forceinline__ uint32_t pk2(float a, float b) {
    __nv_bfloat162 t = __floats2bfloat162_rn(a, b);
    return *reinterpret_cast<uint32_t*>(&t);
}
__device__ __forceinline__ void ldsm_x4(uint32_t* r, uint32_t addr) {
    asm volatile("ldmatrix.sync.aligned.m8n8.x4.shared.b16 {%0,%1,%2,%3}, [%4];"
                 : "=r"(r[0]), "=r"(r[1]), "=r"(r[2]), "=r"(r[3]) : "r"(addr));
}
__device__ __forceinline__ void ldsm_x2(uint32_t* r, uint32_t addr) {
    asm volatile("ldmatrix.sync.aligned.m8n8.x2.shared.b16 {%0,%1}, [%2];"
                 : "=r"(r[0]), "=r"(r[1]) : "r"(addr));
}
__device__ __forceinline__ void mma16816(float* d, const uint32_t* a,
                                         const uint32_t* b) {
    asm volatile(
        "mma.sync.aligned.m16n8k16.row.col.f32.bf16.bf16.f32 "
        "{%0,%1,%2,%3}, {%4,%5,%6,%7}, {%8,%9}, {%0,%1,%2,%3};"
        : "+f"(d[0]), "+f"(d[1]), "+f"(d[2]), "+f"(d[3])
        : "r"(a[0]), "r"(a[1]), "r"(a[2]), "r"(a[3]), "r"(b[0]), "r"(b[1]));
}

// GEMM smem layout (bytes). Rows padded 32->40 bf16 (80B).
#define AHI 0
#define ALO 10240
#define BHI 20480
#define BLO 30720
#define BSO 40960
#define BMO 41472
#define SMEM_TOTAL 41984

// ===========================================================================
// 0) prep: zero hist + weight transpose/split + x -> fp16 copy
// ===========================================================================
__global__ void prep_kernel(const float* __restrict__ x,
                            const float* __restrict__ Wself,
                            const float* __restrict__ Wmsg) {
    int tid = blockIdx.x * blockDim.x + threadIdx.x;
    if (tid < N_NODES) g_deg[tid] = 0;
    if (tid < HDIM * KDIM) {
        int j = tid / KDIM, k = tid % KDIM;
        float v = (k < HDIM) ? Wself[k * HDIM + j] : Wmsg[(k - HDIM) * HDIM + j];
        __nv_bfloat16 h = __float2bfloat16(v);
        g_Wt_hi[tid] = h;
        g_Wt_lo[tid] = __float2bfloat16(v - __bfloat162float(h));
    }
    const int total4 = N_NODES * HDIM / 4;     // 3.2M float4 groups
    const int stride = gridDim.x * blockDim.x;
    for (int i = tid; i < total4; i += stride) {
        float4 f = __ldg(reinterpret_cast<const float4*>(x) + i);
        __half2 h0 = __floats2half2_rn(f.x, f.y);
        __half2 h1 = __floats2half2_rn(f.z, f.w);
        uint2 u;
        u.x = *reinterpret_cast<uint32_t*>(&h0);
        u.y = *reinterpret_cast<uint32_t*>(&h1);
        reinterpret_cast<uint2*>(g_xh)[i] = u;
    }
}

// ===========================================================================
// 1) degree histogram
// ===========================================================================
__global__ void hist_kernel(const int* __restrict__ ei) {
    int e = blockIdx.x * blockDim.x + threadIdx.x;
    if (e < N_EDGES) atomicAdd(&g_deg[__ldg(&ei[N_EDGES + e])], 1);
}

// ===========================================================================
// 2) scan: block-local exclusive in g_off, scanned block bases in g_bsum
// ===========================================================================
__device__ __forceinline__ int warp_incl_scan(int v, int lane) {
#pragma unroll
    for (int d = 1; d < 32; d <<= 1) {
        int t = __shfl_up_sync(0xffffffffu, v, d);
        if (lane >= d) v += t;
    }
    return v;
}
__global__ void scan1_kernel() {
    __shared__ int wsum[32];
    int i = blockIdx.x * 1024 + threadIdx.x;
    int lane = threadIdx.x & 31, w = threadIdx.x >> 5;
    int v = (i < N_NODES) ? g_deg[i] : 0;
    int inc = warp_incl_scan(v, lane);
    if (lane == 31) wsum[w] = inc;
    __syncthreads();
    if (w == 0) {
        int s = wsum[lane];
        int si = warp_incl_scan(s, lane);
        wsum[lane] = si - s;
    }
    __syncthreads();
    int excl = inc - v + wsum[w];
    if (i < N_NODES) g_off[i] = excl;              // block-local exclusive
    if (threadIdx.x == 1023) g_bsum[blockIdx.x] = excl + v;
}
__global__ void scan2_kernel() {
    __shared__ int wsum[4];
    int i = threadIdx.x;
    int lane = i & 31, w = i >> 5;
    int v = (i < NB) ? g_bsum[i] : 0;
    int inc = warp_incl_scan(v, lane);
    if (lane == 31) wsum[w] = inc;
    __syncthreads();
    if (i == 0) {
        int c = 0;
#pragma unroll
        for (int k = 0; k < 4; k++) { int t = wsum[k]; wsum[k] = c; c += t; }
    }
    __syncthreads();
    if (i < NB) g_bsum[i] = inc - v + wsum[w];     // exclusive block bases
}

// ===========================================================================
// 3) reorder: ticket = block-local atomic + scanned block base.
// ===========================================================================
__global__ void reorder_kernel(const int* __restrict__ ei) {
    int e = blockIdx.x * blockDim.x + threadIdx.x;
    if (e >= N_EDGES) return;
    int src = __ldg(&ei[e]);
    int dst = __ldg(&ei[N_EDGES + e]);
    int pos = atomicAdd(&g_off[dst], 1) + __ldg(&g_bsum[dst >> 10]);
    g_rec[pos] = make_int2(src, e);
}

// ===========================================================================
// 4) gather-accumulate: one warp per dst node, fp16 x rows (half traffic),
//    fp32 register accumulation, 4-deep edge pipeline. NO atomics.
// ===========================================================================
__device__ __forceinline__ float4 ld_xh(int src, int lane) {
    uint2 u = __ldg(reinterpret_cast<const uint2*>(
        g_xh + (size_t)src * HDIM + lane * 4));
    float2 a = __half22float2(*reinterpret_cast<__half2*>(&u.x));
    float2 b = __half22float2(*reinterpret_cast<__half2*>(&u.y));
    return make_float4(a.x, a.y, b.x, b.y);
}

__global__ void __launch_bounds__(256)
gather_kernel(const float* __restrict__ ea) {
    int gw   = (blockIdx.x * blockDim.x + threadIdx.x) >> 5;
    int lane = threadIdx.x & 31;
    int nw   = (gridDim.x * blockDim.x) >> 5;
    for (int n = gw; n < N_NODES; n += nw) {
        int beg = (n == 0) ? 0
                : __ldg(&g_off[n - 1]) + __ldg(&g_bsum[(n - 1) >> 10]);
        int end = __ldg(&g_off[n]) + __ldg(&g_bsum[n >> 10]);
        float4 ax = make_float4(0.f, 0.f, 0.f, 0.f);
        float4 ae = make_float4(0.f, 0.f, 0.f, 0.f);
        int i = beg;
        for (; i + 3 < end; i += 4) {
            int2 r0 = __ldg(&g_rec[i]);
            int2 r1 = __ldg(&g_rec[i + 1]);
            int2 r2 = __ldg(&g_rec[i + 2]);
            int2 r3 = __ldg(&g_rec[i + 3]);
            float4 v0 = ld_xh(r0.x, lane);
            float4 v1 = ld_xh(r1.x, lane);
            float4 v2 = ld_xh(r2.x, lane);
            float4 v3 = ld_xh(r3.x, lane);
            ax.x += (v0.x + v1.x) + (v2.x + v3.x);
            ax.y += (v0.y + v1.y) + (v2.y + v3.y);
            ax.z += (v0.z + v1.z) + (v2.z + v3.z);
            ax.w += (v0.w + v1.w) + (v2.w + v3.w);
            if (lane < 8) {
                float4 w0 = __ldg(&reinterpret_cast<const float4*>(ea + (size_t)r0.y * EDIM)[lane]);
                float4 w1 = __ldg(&reinterpret_cast<const float4*>(ea + (size_t)r1.y * EDIM)[lane]);
                float4 w2 = __ldg(&reinterpret_cast<const float4*>(ea + (size_t)r2.y * EDIM)[lane]);
                float4 w3 = __ldg(&reinterpret_cast<const float4*>(ea + (size_t)r3.y * EDIM)[lane]);
                ae.x += (w0.x + w1.x) + (w2.x + w3.x);
                ae.y += (w0.y + w1.y) + (w2.y + w3.y);
                ae.z += (w0.z + w1.z) + (w2.z + w3.z);
                ae.w += (w0.w + w1.w) + (w2.w + w3.w);
            }
        }
        for (; i < end; i++) {
            int2 r0 = __ldg(&g_rec[i]);
            float4 v0 = ld_xh(r0.x, lane);
            ax.x += v0.x; ax.y += v0.y; ax.z += v0.z; ax.w += v0.w;
            if (lane < 8) {
                float4 w0 = __ldg(&reinterpret_cast<const float4*>(ea + (size_t)r0.y * EDIM)[lane]);
                ae.x += w0.x; ae.y += w0.y; ae.z += w0.z; ae.w += w0.w;
            }
        }
        reinterpret_cast<float4*>(g_Sx + (size_t)n * HDIM)[lane] = ax;
        if (lane < 8)
            reinterpret_cast<float4*>(g_Se + (size_t)n * EDIM)[lane] = ae;
    }
}

// ===========================================================================
// 5) mma.sync bf16 2-split GEMM (R5-proven): 128x128 tile, 42KB smem
// ===========================================================================
__global__ void __launch_bounds__(256)
node_gemm_mma(const float* __restrict__ x,
              const float* __restrict__ bself,
              const float* __restrict__ bmsg,
              float* __restrict__ out) {
    __shared__ __align__(16) unsigned char sm[SMEM_TOTAL];
    const uint32_t sbase = smem_u32(sm);

    const int tid = threadIdx.x;
    const int lane = tid & 31;
    const int wid = tid >> 5;
    const int warp_m = wid & 3;
    const int warp_n = wid >> 2;

    float* bs = reinterpret_cast<float*>(sm + BSO);
    float* bm = reinterpret_cast<float*>(sm + BMO);
    if (tid < HDIM) { bs[tid] = bself[tid]; bm[tid] = bmsg[tid]; }

    const int n0 = blockIdx.x * 128;

    const int kp = tid & 15;
    const int arow0 = tid >> 4;
    float2 av[8];
    uint4 bhv[2], blv[2];

    float acc[2][8][4];
#pragma unroll
    for (int a = 0; a < 2; a++)
#pragma unroll
        for (int b = 0; b < 8; b++)
#pragma unroll
            for (int c = 0; c < 4; c++) acc[a][b][c] = 0.f;

    auto stage = [&](int c) {
        const int kb = c * 32;
        const float* asrc;
        int astr;
        if (kb < 128)      { asrc = x    + kb;       astr = HDIM; }
        else if (kb < 256) { asrc = g_Sx + kb - 128; astr = HDIM; }
        else               { asrc = g_Se;            astr = EDIM; }
#pragma unroll
        for (int t = 0; t < 8; t++) {
            int gn = n0 + arow0 + t * 16;
            av[t] = (gn < N_NODES)
                ? *reinterpret_cast<const float2*>(asrc + (size_t)gn * astr + kp * 2)
                : make_float2(0.f, 0.f);
        }
#pragma unroll
        for (int t = 0; t < 2; t++) {
            int q = tid + t * 256;
            int j = q >> 2, sub = q & 3;
            size_t o = (size_t)j * KDIM + kb + sub * 8;
            bhv[t] = *reinterpret_cast<const uint4*>(g_Wt_hi + o);
            blv[t] = *reinterpret_cast<const uint4*>(g_Wt_lo + o);
        }
    };
    auto commit = [&]() {
#pragma unroll
        for (int t = 0; t < 8; t++) {
            int row = arow0 + t * 16;
            float vx = av[t].x, vy = av[t].y;
            __nv_bfloat16 hx = __float2bfloat16(vx);
            __nv_bfloat16 hy = __float2bfloat16(vy);
            float lx = vx - __bfloat162float(hx);
            float ly = vy - __bfloat162float(hy);
            __nv_bfloat162 hp; hp.x = hx; hp.y = hy;
            *reinterpret_cast<uint32_t*>(sm + AHI + row * 80 + kp * 4) =
                *reinterpret_cast<uint32_t*>(&hp);
            *reinterpret_cast<uint32_t*>(sm + ALO + row * 80 + kp * 4) =
                pk2(lx, ly);
        }
#pragma unroll
        for (int t = 0; t < 2; t++) {
            int q = tid + t * 256;
            int j = q >> 2, sub = q & 3;
            *reinterpret_cast<uint4*>(sm + BHI + j * 80 + sub * 16) = bhv[t];
            *reinterpret_cast<uint4*>(sm + BLO + j * 80 + sub * 16) = blv[t];
        }
    };

    const uint32_t a_row_off = (warp_m * 32 + (lane & 15)) * 80 + (lane >> 4) * 16;
    const uint32_t b_row_off = (warp_n * 64 + (lane & 7)) * 80 + ((lane >> 3) & 1) * 16;

    stage(0);
    __syncthreads();
    commit();
    __syncthreads();

    for (int c = 0; c < NCHUNK; c++) {
        if (c + 1 < NCHUNK) stage(c + 1);

#pragma unroll
        for (int ks = 0; ks < 2; ks++) {
            uint32_t ah[2][4], al[2][4];
#pragma unroll
            for (int mf = 0; mf < 2; mf++) {
                uint32_t ao = a_row_off + mf * 16 * 80 + ks * 32;
                ldsm_x4(ah[mf], sbase + AHI + ao);
                ldsm_x4(al[mf], sbase + ALO + ao);
            }
#pragma unroll
            for (int nf = 0; nf < 8; nf++) {
                uint32_t bo = b_row_off + nf * 8 * 80 + ks * 32;
                uint32_t bh[2], bl[2];
                ldsm_x2(bh, sbase + BHI + bo);
                ldsm_x2(bl, sbase + BLO + bo);
#pragma unroll
                for (int mf = 0; mf < 2; mf++) {
                    mma16816(acc[mf][nf], ah[mf], bh);
                    mma16816(acc[mf][nf], ah[mf], bl);
                    mma16816(acc[mf][nf], al[mf], bh);
                }
            }
        }
        __syncthreads();
        if (c + 1 < NCHUNK) {
            commit();
            __syncthreads();
        }
    }

    const int gid = lane >> 2, tig = lane & 3;
#pragma unroll
    for (int mf = 0; mf < 2; mf++) {
#pragma unroll
        for (int rr = 0; rr < 2; rr++) {
            int row = warp_m * 32 + mf * 16 + rr * 8 + gid;
            int gn = n0 + row;
            if (gn >= N_NODES) continue;
            float degf = (float)g_deg[gn];
#pragma unroll
            for (int nf = 0; nf < 8; nf++) {
                int j = warp_n * 64 + nf * 8 + tig * 2;
                float2 o;
                o.x = fmaxf(acc[mf][nf][rr * 2 + 0] + bs[j]     + degf * bm[j],     0.f);
                o.y = fmaxf(acc[mf][nf][rr * 2 + 1] + bs[j + 1] + degf * bm[j + 1], 0.f);
                *reinterpret_cast<float2*>(out + (size_t)gn * HDIM + j) = o;
            }
        }
    }
}

// ---------------------------------------------------------------------------
extern "C" void kernel_launch(void* const* d_in, const int* in_sizes, int n_in,
                              void* d_out, int out_size) {
    const float* x     = (const float*)d_in[0];
    const int*   ei    = (const int*)  d_in[1];
    const float* ea    = (const float*)d_in[2];
    const float* Wself = (const float*)d_in[3];
    const float* bself = (const float*)d_in[4];
    const float* Wmsg  = (const float*)d_in[5];
    const float* bmsg  = (const float*)d_in[6];
    float* out = (float*)d_out;

    prep_kernel<<<2048, 256>>>(x, Wself, Wmsg);                     // 0
    hist_kernel<<<(N_EDGES + 511) / 512, 512>>>(ei);                // 1
    scan1_kernel<<<NB, 1024>>>();                                   // 2
    scan2_kernel<<<1, 128>>>();                                     // 3
    reorder_kernel<<<(N_EDGES + 511) / 512, 512>>>(ei);             // 4
    gather_kernel<<<148 * 12, 256>>>(ea);                           // 5 (ncu -s 5)
    node_gemm_mma<<<N_TILES, 256>>>(x, bself, bmsg, out);           // 6
}

// round 9
// speedup vs baseline: 3.3517x; 1.2940x over previous
#include <cuda_runtime.h>
#include <cuda_fp16.h>
#include <cstdint>

#define N_NODES 100000
#define N_EDGES 1600000
#define HDIM 128
#define EDIM 32
#define KDIM 288                 // 128 + 128 + 32 = 9 * 32
#define NCHUNK 9
#define N_TILES ((N_NODES + 127) / 128)   // 782
#define NB 98

// ---------------- device scratch (allocation-free rule) ----------------
__device__ __half g_xh[N_NODES * HDIM];    // fp16 copy of x
__device__ __half g_SxH[N_NODES * HDIM];   // fp16 segment_sum(x[src], dst)
__device__ __half g_SeH[N_NODES * EDIM];   // fp16 segment_sum(edge_attr, dst)
__device__ __half g_Wt[HDIM * KDIM];       // fp16 Wt[j][k] = Wcat[k][j]
__device__ int    g_deg[N_NODES];
__device__ int    g_off[N_NODES];
__device__ int    g_bsum[NB];
__device__ int2   g_rec[N_EDGES];

// ---------------- helpers ----------------
__device__ __forceinline__ uint32_t smem_u32(const void* p) {
    uint32_t a;
    asm("{ .reg .u64 t; cvta.to.shared.u64 t, %1; cvt.u32.u64 %0, t; }"
        : "=r"(a) : "l"(p));
    return a;
}
__device__ __forceinline__ void ldsm_x4(uint32_t* r, uint32_t addr) {
    asm volatile("ldmatrix.sync.aligned.m8n8.x4.shared.b16 {%0,%1,%2,%3}, [%4];"
                 : "=r"(r[0]), "=r"(r[1]), "=r"(r[2]), "=r"(r[3]) : "r"(addr));
}
__device__ __forceinline__ void ldsm_x2(uint32_t* r, uint32_t addr) {
    asm volatile("ldmatrix.sync.aligned.m8n8.x2.shared.b16 {%0,%1}, [%2];"
                 : "=r"(r[0]), "=r"(r[1]) : "r"(addr));
}
__device__ __forceinline__ void mma16816h(float* d, const uint32_t* a,
                                          const uint32_t* b) {
    asm volatile(
        "mma.sync.aligned.m16n8k16.row.col.f32.f16.f16.f32 "
        "{%0,%1,%2,%3}, {%4,%5,%6,%7}, {%8,%9}, {%0,%1,%2,%3};"
        : "+f"(d[0]), "+f"(d[1]), "+f"(d[2]), "+f"(d[3])
        : "r"(a[0]), "r"(a[1]), "r"(a[2]), "r"(a[3]), "r"(b[0]), "r"(b[1]));
}
__device__ __forceinline__ uint32_t pkh2(float a, float b) {
    __half2 t = __floats2half2_rn(a, b);
    return *reinterpret_cast<uint32_t*>(&t);
}

// GEMM smem layout (bytes): A/B chunk tiles 128 rows x 80B pitch (fp16)
#define SM_A  0
#define SM_B  10240
#define SM_BS 20480
#define SM_BM 20992
#define SMEM_TOTAL 21504

// ===========================================================================
// 0) prep: zero hist + fp16 weight transpose + x -> fp16 copy
// ===========================================================================
__global__ void prep_kernel(const float* __restrict__ x,
                            const float* __restrict__ Wself,
                            const float* __restrict__ Wmsg) {
    int tid = blockIdx.x * blockDim.x + threadIdx.x;
    if (tid < N_NODES) g_deg[tid] = 0;
    if (tid < HDIM * KDIM) {
        int j = tid / KDIM, k = tid % KDIM;
        float v = (k < HDIM) ? Wself[k * HDIM + j] : Wmsg[(k - HDIM) * HDIM + j];
        g_Wt[tid] = __float2half(v);
    }
    const int total4 = N_NODES * HDIM / 4;
    const int stride = gridDim.x * blockDim.x;
    for (int i = tid; i < total4; i += stride) {
        float4 f = __ldg(reinterpret_cast<const float4*>(x) + i);
        uint2 u;
        u.x = pkh2(f.x, f.y);
        u.y = pkh2(f.z, f.w);
        reinterpret_cast<uint2*>(g_xh)[i] = u;
    }
}

// ===========================================================================
// 1) degree histogram
// ===========================================================================
__global__ void hist_kernel(const int* __restrict__ ei) {
    int e = blockIdx.x * blockDim.x + threadIdx.x;
    if (e < N_EDGES) atomicAdd(&g_deg[__ldg(&ei[N_EDGES + e])], 1);
}

// ===========================================================================
// 2) scan: block-local exclusive in g_off, scanned block bases in g_bsum
// ===========================================================================
__device__ __forceinline__ int warp_incl_scan(int v, int lane) {
#pragma unroll
    for (int d = 1; d < 32; d <<= 1) {
        int t = __shfl_up_sync(0xffffffffu, v, d);
        if (lane >= d) v += t;
    }
    return v;
}
__global__ void scan1_kernel() {
    __shared__ int wsum[32];
    int i = blockIdx.x * 1024 + threadIdx.x;
    int lane = threadIdx.x & 31, w = threadIdx.x >> 5;
    int v = (i < N_NODES) ? g_deg[i] : 0;
    int inc = warp_incl_scan(v, lane);
    if (lane == 31) wsum[w] = inc;
    __syncthreads();
    if (w == 0) {
        int s = wsum[lane];
        int si = warp_incl_scan(s, lane);
        wsum[lane] = si - s;
    }
    __syncthreads();
    int excl = inc - v + wsum[w];
    if (i < N_NODES) g_off[i] = excl;
    if (threadIdx.x == 1023) g_bsum[blockIdx.x] = excl + v;
}
__global__ void scan2_kernel() {
    __shared__ int wsum[4];
    int i = threadIdx.x;
    int lane = i & 31, w = i >> 5;
    int v = (i < NB) ? g_bsum[i] : 0;
    int inc = warp_incl_scan(v, lane);
    if (lane == 31) wsum[w] = inc;
    __syncthreads();
    if (i == 0) {
        int c = 0;
#pragma unroll
        for (int k = 0; k < 4; k++) { int t = wsum[k]; wsum[k] = c; c += t; }
    }
    __syncthreads();
    if (i < NB) g_bsum[i] = inc - v + wsum[w];
}

// ===========================================================================
// 3) reorder
// ===========================================================================
__global__ void reorder_kernel(const int* __restrict__ ei) {
    int e = blockIdx.x * blockDim.x + threadIdx.x;
    if (e >= N_EDGES) return;
    int src = __ldg(&ei[e]);
    int dst = __ldg(&ei[N_EDGES + e]);
    int pos = atomicAdd(&g_off[dst], 1) + __ldg(&g_bsum[dst >> 10]);
    g_rec[pos] = make_int2(src, e);
}

// ===========================================================================
// 4) gather-accumulate: fp16 x rows, fp32 accumulation, fp16 outputs
// ===========================================================================
__device__ __forceinline__ float4 ld_xh(int src, int lane) {
    uint2 u = __ldg(reinterpret_cast<const uint2*>(
        g_xh + (size_t)src * HDIM + lane * 4));
    float2 a = __half22float2(*reinterpret_cast<__half2*>(&u.x));
    float2 b = __half22float2(*reinterpret_cast<__half2*>(&u.y));
    return make_float4(a.x, a.y, b.x, b.y);
}

__global__ void __launch_bounds__(256)
gather_kernel(const float* __restrict__ ea) {
    int gw   = (blockIdx.x * blockDim.x + threadIdx.x) >> 5;
    int lane = threadIdx.x & 31;
    int nw   = (gridDim.x * blockDim.x) >> 5;
    for (int n = gw; n < N_NODES; n += nw) {
        int beg = (n == 0) ? 0
                : __ldg(&g_off[n - 1]) + __ldg(&g_bsum[(n - 1) >> 10]);
        int end = __ldg(&g_off[n]) + __ldg(&g_bsum[n >> 10]);
        float4 ax = make_float4(0.f, 0.f, 0.f, 0.f);
        float4 ae = make_float4(0.f, 0.f, 0.f, 0.f);
        int i = beg;
        for (; i + 3 < end; i += 4) {
            int2 r0 = __ldg(&g_rec[i]);
            int2 r1 = __ldg(&g_rec[i + 1]);
            int2 r2 = __ldg(&g_rec[i + 2]);
            int2 r3 = __ldg(&g_rec[i + 3]);
            float4 v0 = ld_xh(r0.x, lane);
            float4 v1 = ld_xh(r1.x, lane);
            float4 v2 = ld_xh(r2.x, lane);
            float4 v3 = ld_xh(r3.x, lane);
            ax.x += (v0.x + v1.x) + (v2.x + v3.x);
            ax.y += (v0.y + v1.y) + (v2.y + v3.y);
            ax.z += (v0.z + v1.z) + (v2.z + v3.z);
            ax.w += (v0.w + v1.w) + (v2.w + v3.w);
            if (lane < 8) {
                float4 w0 = __ldg(&reinterpret_cast<const float4*>(ea + (size_t)r0.y * EDIM)[lane]);
                float4 w1 = __ldg(&reinterpret_cast<const float4*>(ea + (size_t)r1.y * EDIM)[lane]);
                float4 w2 = __ldg(&reinterpret_cast<const float4*>(ea + (size_t)r2.y * EDIM)[lane]);
                float4 w3 = __ldg(&reinterpret_cast<const float4*>(ea + (size_t)r3.y * EDIM)[lane]);
                ae.x += (w0.x + w1.x) + (w2.x + w3.x);
                ae.y += (w0.y + w1.y) + (w2.y + w3.y);
                ae.z += (w0.z + w1.z) + (w2.z + w3.z);
                ae.w += (w0.w + w1.w) + (w2.w + w3.w);
            }
        }
        for (; i < end; i++) {
            int2 r0 = __ldg(&g_rec[i]);
            float4 v0 = ld_xh(r0.x, lane);
            ax.x += v0.x; ax.y += v0.y; ax.z += v0.z; ax.w += v0.w;
            if (lane < 8) {
                float4 w0 = __ldg(&reinterpret_cast<const float4*>(ea + (size_t)r0.y * EDIM)[lane]);
                ae.x += w0.x; ae.y += w0.y; ae.z += w0.z; ae.w += w0.w;
            }
        }
        uint2 ox;
        ox.x = pkh2(ax.x, ax.y);
        ox.y = pkh2(ax.z, ax.w);
        reinterpret_cast<uint2*>(g_SxH + (size_t)n * HDIM)[lane] = ox;
        if (lane < 8) {
            uint2 oe;
            oe.x = pkh2(ae.x, ae.y);
            oe.y = pkh2(ae.z, ae.w);
            reinterpret_cast<uint2*>(g_SeH + (size_t)n * EDIM)[lane] = oe;
        }
    }
}

// ===========================================================================
// 5) single-product fp16 mma GEMM: out = relu([x|Sx|Se]@W + b_self + deg*b_msg)
//    A/B staged as raw fp16 uint4 copies (no conversion in hot loop).
// ===========================================================================
__global__ void __launch_bounds__(256)
node_gemm_mma(const float* __restrict__ bself,
              const float* __restrict__ bmsg,
              float* __restrict__ out) {
    __shared__ __align__(16) unsigned char sm[SMEM_TOTAL];
    const uint32_t sbase = smem_u32(sm);

    const int tid = threadIdx.x;
    const int lane = tid & 31;
    const int wid = tid >> 5;
    const int warp_m = wid & 3;
    const int warp_n = wid >> 2;

    float* bs = reinterpret_cast<float*>(sm + SM_BS);
    float* bm = reinterpret_cast<float*>(sm + SM_BM);
    if (tid < HDIM) { bs[tid] = bself[tid]; bm[tid] = bmsg[tid]; }

    const int n0 = blockIdx.x * 128;

    uint4 av[2], bv[2];
    float acc[2][8][4];
#pragma unroll
    for (int a = 0; a < 2; a++)
#pragma unroll
        for (int b = 0; b < 8; b++)
#pragma unroll
            for (int c = 0; c < 4; c++) acc[a][b][c] = 0.f;

    // stage chunk c: A rows from fp16 sources, B rows from g_Wt (raw copies)
    auto stage = [&](int c) {
        const __half* asrc;
        int astr;
        if (c < 4)      { asrc = g_xh  + 32 * c;       astr = HDIM; }
        else if (c < 8) { asrc = g_SxH + 32 * (c - 4); astr = HDIM; }
        else            { asrc = g_SeH;                astr = EDIM; }
#pragma unroll
        for (int t = 0; t < 2; t++) {
            int idx = tid + t * 256;          // 0..511
            int row = idx >> 2, q = idx & 3;  // 128 rows x 4 (8-half) groups
            int gn = n0 + row;
            av[t] = (gn < N_NODES)
                ? __ldg(reinterpret_cast<const uint4*>(
                      asrc + (size_t)gn * astr + q * 8))
                : make_uint4(0u, 0u, 0u, 0u);
            bv[t] = __ldg(reinterpret_cast<const uint4*>(
                g_Wt + (size_t)row * KDIM + c * 32 + q * 8));
        }
    };
    auto commit = [&]() {
#pragma unroll
        for (int t = 0; t < 2; t++) {
            int idx = tid + t * 256;
            int row = idx >> 2, q = idx & 3;
            *reinterpret_cast<uint4*>(sm + SM_A + row * 80 + q * 16) = av[t];
            *reinterpret_cast<uint4*>(sm + SM_B + row * 80 + q * 16) = bv[t];
        }
    };

    const uint32_t a_row_off = (warp_m * 32 + (lane & 15)) * 80 + (lane >> 4) * 16;
    const uint32_t b_row_off = (warp_n * 64 + (lane & 7)) * 80 + ((lane >> 3) & 1) * 16;

    stage(0);
    __syncthreads();   // biases visible
    commit();
    __syncthreads();

    for (int c = 0; c < NCHUNK; c++) {
        if (c + 1 < NCHUNK) stage(c + 1);

#pragma unroll
        for (int ks = 0; ks < 2; ks++) {
            uint32_t ah[2][4];
#pragma unroll
            for (int mf = 0; mf < 2; mf++)
                ldsm_x4(ah[mf], sbase + SM_A + a_row_off + mf * 16 * 80 + ks * 32);
#pragma unroll
            for (int nf = 0; nf < 8; nf++) {
                uint32_t bh[2];
                ldsm_x2(bh, sbase + SM_B + b_row_off + nf * 8 * 80 + ks * 32);
                mma16816h(acc[0][nf], ah[0], bh);
                mma16816h(acc[1][nf], ah[1], bh);
            }
        }
        __syncthreads();
        if (c + 1 < NCHUNK) {
            commit();
            __syncthreads();
        }
    }

    // ---- epilogue: bias + deg*b_msg + relu ----
    const int gid = lane >> 2, tig = lane & 3;
#pragma unroll
    for (int mf = 0; mf < 2; mf++) {
#pragma unroll
        for (int rr = 0; rr < 2; rr++) {
            int row = warp_m * 32 + mf * 16 + rr * 8 + gid;
            int gn = n0 + row;
            if (gn >= N_NODES) continue;
            float degf = (float)g_deg[gn];
#pragma unroll
            for (int nf = 0; nf < 8; nf++) {
                int j = warp_n * 64 + nf * 8 + tig * 2;
                float2 o;
                o.x = fmaxf(acc[mf][nf][rr * 2 + 0] + bs[j]     + degf * bm[j],     0.f);
                o.y = fmaxf(acc[mf][nf][rr * 2 + 1] + bs[j + 1] + degf * bm[j + 1], 0.f);
                *reinterpret_cast<float2*>(out + (size_t)gn * HDIM + j) = o;
            }
        }
    }
}

// ---------------------------------------------------------------------------
extern "C" void kernel_launch(void* const* d_in, const int* in_sizes, int n_in,
                              void* d_out, int out_size) {
    const float* x     = (const float*)d_in[0];
    const int*   ei    = (const int*)  d_in[1];
    const float* ea    = (const float*)d_in[2];
    const float* Wself = (const float*)d_in[3];
    const float* bself = (const float*)d_in[4];
    const float* Wmsg  = (const float*)d_in[5];
    const float* bmsg  = (const float*)d_in[6];
    float* out = (float*)d_out;

    prep_kernel<<<2048, 256>>>(x, Wself, Wmsg);                     // 0
    hist_kernel<<<(N_EDGES + 511) / 512, 512>>>(ei);                // 1
    scan1_kernel<<<NB, 1024>>>();                                   // 2
    scan2_kernel<<<1, 128>>>();                                     // 3
    reorder_kernel<<<(N_EDGES + 511) / 512, 512>>>(ei);             // 4
    gather_kernel<<<148 * 12, 256>>>(ea);                           // 5 (ncu -s 5)
    node_gemm_mma<<<N_TILES, 256>>>(bself, bmsg, out);              // 6
}